// round 12
// baseline (speedup 1.0000x reference)
#include <cuda_runtime.h>
#include <math.h>
#include <stdint.h>

#define SS 64
#define NN 256
#define CC 3
#define BB 64
#define LL 2048
#define WW (LL - SS + 1)   /* 1985 */
#define WPAD 2048
#define NSTAGE 4
#define PAIRS 32           /* shapelet pairs per stage (64 shapelets) */
#define XROW 2112          /* staged x pairs per channel */
#define THREADS 256

typedef unsigned long long ull;

__device__ float g_winsq[BB * CC * WPAD];
__device__ ull   g_shp[NSTAGE * CC * PAIRS * SS];   /* interleaved (n0,n1) pairs */
__device__ float2 g_sqn[NSTAGE * CC * PAIRS];
__constant__ ull c_shp[CC * PAIRS * SS];            /* 49152 B, one stage */

// ---------- packed f32x2 helpers ----------
__device__ __forceinline__ ull pack2(float v) {
    ull r; asm("mov.b64 %0, {%1, %1};" : "=l"(r) : "f"(v)); return r;
}
__device__ __forceinline__ ull packab(float a, float b) {
    ull r; asm("mov.b64 %0, {%1, %2};" : "=l"(r) : "f"(a), "f"(b)); return r;
}
__device__ __forceinline__ void fma2(ull& d, ull a, ull b) {
    asm("fma.rn.f32x2 %0, %1, %2, %0;" : "+l"(d) : "l"(a), "l"(b));
}
__device__ __forceinline__ ull add2(ull a, ull b) {
    ull r; asm("add.rn.f32x2 %0, %1, %2;" : "=l"(r) : "l"(a), "l"(b)); return r;
}
__device__ __forceinline__ void unpack2(float& lo, float& hi, ull v) {
    asm("mov.b64 {%0, %1}, %2;" : "=f"(lo), "=f"(hi) : "l"(v));
}
__device__ __forceinline__ float sqrt_ap(float v) {
    float r; asm("sqrt.approx.f32 %0, %1;" : "=f"(r) : "f"(v)); return r;
}
__device__ __forceinline__ uint32_t smem_u32(const void* p) {
    uint32_t a;
    asm("{ .reg .u64 t; cvta.to.shared.u64 t, %1; cvt.u32.u64 %0, t; }" : "=r"(a) : "l"(p));
    return a;
}

// ---------- kernel 1: window squared norms ----------
__global__ void winsq_kernel(const float* __restrict__ x) {
    int b = blockIdx.x, c = blockIdx.y;
    __shared__ float xs[LL];
    const float* xp = x + (b * CC + c) * LL;
    for (int i = threadIdx.x; i < LL; i += blockDim.x) xs[i] = xp[i];
    __syncthreads();
    for (int w = threadIdx.x; w < WPAD; w += blockDim.x) {
        float s = 0.f;
        if (w < WW) {
#pragma unroll 16
            for (int k = 0; k < SS; k++) { float v = xs[w + k]; s = fmaf(v, v, s); }
        }
        g_winsq[(b * CC + c) * WPAD + w] = s;
    }
}

// ---------- kernel 2: shapelet pair interleave + norms ----------
__global__ void shp_prep(const float* __restrict__ shp) {
    int st = blockIdx.x, c = blockIdx.y;
    for (int i = threadIdx.x; i < PAIRS * SS; i += blockDim.x) {
        int p = i >> 6, s = i & 63;
        int n0 = st * 64 + 2 * p;
        float a = shp[(c * NN + n0) * SS + s];
        float b = shp[(c * NN + n0 + 1) * SS + s];
        ((float2*)g_shp)[(st * CC + c) * (PAIRS * SS) + i] = make_float2(a, b);
    }
    if (threadIdx.x < PAIRS) {
        int p = threadIdx.x;
        int n0 = st * 64 + 2 * p;
        float s0 = 0.f, s1 = 0.f;
#pragma unroll 8
        for (int s = 0; s < SS; s++) {
            float a = shp[(c * NN + n0) * SS + s];
            float b = shp[(c * NN + n0 + 1) * SS + s];
            s0 = fmaf(a, a, s0); s1 = fmaf(b, b, s1);
        }
        g_sqn[(st * CC + c) * PAIRS + p] = make_float2(s0, s1);
    }
}

// ---------- kernel 3: main (one shapelet pair per block) ----------
__global__ __launch_bounds__(THREADS, 3) void main_kernel(
    const float* __restrict__ x, float* __restrict__ out, int stage)
{
    extern __shared__ float2 xs[];   /* CC * XROW duplicated pairs, 50688 B */
    __shared__ float rmin[8][2];

    const int pair = blockIdx.x;     // 0..31
    const int b    = blockIdx.y;     // 0..63
    const int tid  = threadIdx.x;
    const int lane = tid & 31;
    const int wk   = tid >> 5;       // warp -> 256-w slice

    // Stage x rows as duplicated pairs (clamped tail)
    for (int c = 0; c < CC; c++) {
        const float* xp = x + (b * CC + c) * LL;
        for (int k = tid; k < XROW; k += THREADS) {
            float v = xp[min(k, LL - 1)];
            xs[c * XROW + k] = make_float2(v, v);
        }
    }
    __syncthreads();

    const uint32_t xs_base = smem_u32(xs);
    const int wr = 256 * wk + 2 * lane;     // w = wr + 64*j + e
    const ull NEG2 = pack2(-2.0f);
    const float INF = __int_as_float(0x7f800000);

    float t0[8], t1[8];
#pragma unroll
    for (int s = 0; s < 8; s++) { t0[s] = 0.f; t1[s] = 0.f; }

#pragma unroll 1
    for (int c = 0; c < CC; c++) {
        const uint32_t xaddr = xs_base + (uint32_t)(c * XROW + wr) * 8u;
        const ull* shrow = &c_shp[(c * PAIRS + pair) * SS];

        ull acc[8];
#pragma unroll
        for (int s = 0; s < 8; s++) acc[s] = 0ull;
        ull shA = 0ull;

#pragma unroll
        for (int jb = 0; jb < 4; jb++) {
#pragma unroll
            for (int i = 0; i < 32; i++) {
                ull x0, x1;
                asm("ld.shared.v2.u64 {%0,%1}, [%2];"
                    : "=l"(x0), "=l"(x1)
                    : "r"(xaddr + (uint32_t)((jb * 64 + 2 * i) * 8)));
                ulonglong2 shv = *(const ulonglong2*)(shrow + 2 * i);
                // interior: w slots 2jb (e=0), 2jb+1 (e=1)
                fma2(acc[2 * jb],     x0, shv.x);   // (e0, s0)
                fma2(acc[2 * jb],     x1, shv.y);   // (e0, s0+1)
                fma2(acc[2 * jb + 1], x1, shv.x);   // (e1, s0)
                if (jb > 0 || i > 0) {
                    // (e1, s0-1): same jb when i>0; previous jb's s=63 when i==0
                    fma2(acc[i > 0 ? 2 * jb + 1 : 2 * jb - 1], x0, shA);
                }
                shA = shv.y;
            }
        }
        {   // tail: u = wr+256 feeds (e1, j=3, s=63)
            ull x0;
            asm("ld.shared.u64 %0, [%1];"
                : "=l"(x0) : "r"(xaddr + (uint32_t)(256 * 8)));
            fma2(acc[7], x0, shA);
        }

        // epilogue: d = sqrt(max(ws + sqn - 2*cross, 0)), accumulate over c
        float2 qn = g_sqn[(stage * CC + c) * PAIRS + pair];
        ull sqn2 = packab(qn.x, qn.y);
        const float* wsrow = g_winsq + (b * CC + c) * WPAD;
#pragma unroll
        for (int s = 0; s < 8; s++) {
            int w = wr + 64 * (s >> 1) + (s & 1);
            ull base = add2(pack2(wsrow[w]), sqn2);
            fma2(base, acc[s], NEG2);
            float lo, hi;
            unpack2(lo, hi, base);
            t0[s] += sqrt_ap(fmaxf(lo, 0.f));
            t1[s] += sqrt_ap(fmaxf(hi, 0.f));
        }
    }

    // thread-local min with W mask
    float m0 = INF, m1 = INF;
#pragma unroll
    for (int s = 0; s < 8; s++) {
        int w = wr + 64 * (s >> 1) + (s & 1);
        if (w < WW) { m0 = fminf(m0, t0[s]); m1 = fminf(m1, t1[s]); }
    }
    // warp butterfly over 32 lanes
#pragma unroll
    for (int o = 1; o < 32; o <<= 1) {
        m0 = fminf(m0, __shfl_xor_sync(0xffffffffu, m0, o));
        m1 = fminf(m1, __shfl_xor_sync(0xffffffffu, m1, o));
    }
    if (lane == 0) { rmin[wk][0] = m0; rmin[wk][1] = m1; }
    __syncthreads();
    if (tid < 2) {
        float m = rmin[0][tid];
#pragma unroll
        for (int wq = 1; wq < 8; wq++) m = fminf(m, rmin[wq][tid]);
        out[b * NN + stage * 64 + 2 * pair + tid] = m;
    }
}

extern "C" void kernel_launch(void* const* d_in, const int* in_sizes, int n_in,
                              void* d_out, int out_size) {
    (void)in_sizes; (void)n_in; (void)out_size;
    const float* x   = (const float*)d_in[0];
    const float* shp = (const float*)d_in[1];
    float* out = (float*)d_out;

    const int smem_bytes = CC * XROW * (int)sizeof(float2);
    cudaFuncSetAttribute(main_kernel, cudaFuncAttributeMaxDynamicSharedMemorySize, smem_bytes);

    winsq_kernel<<<dim3(BB, CC), 256>>>(x);
    shp_prep<<<dim3(NSTAGE, CC), 256>>>(shp);

    void* gshp_ptr = nullptr;
    cudaGetSymbolAddress(&gshp_ptr, g_shp);
    const size_t stage_bytes = (size_t)CC * PAIRS * SS * sizeof(ull);  // 49152

    for (int st = 0; st < NSTAGE; st++) {
        cudaMemcpyToSymbolAsync(c_shp,
                                (const char*)gshp_ptr + (size_t)st * stage_bytes,
                                stage_bytes, 0, cudaMemcpyDeviceToDevice, 0);
        main_kernel<<<dim3(PAIRS, BB), THREADS, smem_bytes>>>(x, out, st);
    }
}